// round 15
// baseline (speedup 1.0000x reference)
#include <cuda_runtime.h>
#include <cuda_bf16.h>
#include <mma.h>
#include <cstdint>

using namespace nvcuda;
typedef unsigned int u32;
typedef __nv_bfloat16 bf16;

#define BB 128
#define TT 512
#define FF 128
#define UU 512
#define G3 1536
#define NCTA 128
#define NTHR 512

// SMEM byte offsets
#define OFF_WH   0            // weights hi (<=64KB)
#define OFF_WL   65536        // weights lo
#define OFF_ACT  131072       // 3 buffers x 16384 (hi 8KB + lo 8KB)
#define OFF_CTRL 180224       // 3 mbarriers
#define OFF_SCRA OFF_ACT      // scratch overlays act buffers post-loop
#define OFF_SCRB (OFF_ACT + 18432)
#define SMEM_BYTES 180352

__device__ __align__(128) bf16 g_xhi[(size_t)TT * 4 * BB * 32];   // (t, chunk, b, 32)
__device__ __align__(128) bf16 g_xlo[(size_t)TT * 4 * BB * 32];
__device__ __align__(128) bf16 g_h1hi[2 * 16 * BB * 32];          // (par, chunk, b, 32)
__device__ __align__(128) bf16 g_h1lo[2 * 16 * BB * 32];
__device__ __align__(128) bf16 g_h2hi[2 * 16 * BB * 32];
__device__ __align__(128) bf16 g_h2lo[2 * 16 * BB * 32];
__device__ __align__(128) float g_head[64 * BB];
__device__ __align__(128) int  g_bar[TT + 4];

__device__ __forceinline__ float sigm(float v) { return 1.0f / (1.0f + __expf(-v)); }
__device__ __forceinline__ void bulk_cp(u32 dst, const void* src, u32 mbar) {
    asm volatile("cp.async.bulk.shared::cta.global.mbarrier::complete_tx::bytes [%0], [%1], %2, [%3];"
                 :: "r"(dst), "l"(src), "r"(8192u), "r"(mbar) : "memory");
}
__device__ __forceinline__ void mwait(u32 mb, u32 par) {
    u32 done = 0;
    do {
        asm volatile("{\n\t.reg .pred p;\n\t"
                     "mbarrier.try_wait.parity.acquire.cta.shared::cta.b64 p, [%1], %2, 0x989680;\n\t"
                     "selp.b32 %0,1,0,p;\n\t}" : "=r"(done) : "r"(mb), "r"(par) : "memory");
    } while (!done);
}
__device__ __forceinline__ void grid_barrier(int* bars, int s) {
    __syncthreads();
    if (threadIdx.x == 0) {
        asm volatile("red.release.gpu.global.add.u32 [%0], 1;" :: "l"(bars + s) : "memory");
        int v;
        do { asm volatile("ld.acquire.gpu.global.u32 %0, [%1];" : "=r"(v) : "l"(bars + s) : "memory"); }
        while (v < NCTA);
        if (s >= 1)
            asm volatile("st.global.relaxed.gpu.u32 [%0], %1;" :: "l"(bars + s - 1), "r"(0) : "memory");
    }
    __syncthreads();
}

typedef wmma::fragment<wmma::matrix_a, 16, 16, 16, bf16, wmma::row_major> FragA;
typedef wmma::fragment<wmma::matrix_b, 16, 16, 16, bf16, wmma::row_major> FragB;
typedef wmma::fragment<wmma::accumulator, 16, 16, 16, float> FragC;

__global__ void __launch_bounds__(NTHR, 1) gru_wmma(
    const float* __restrict__ W1, const float* __restrict__ U1,
    const float* __restrict__ bi1, const float* __restrict__ br1,
    const float* __restrict__ W2, const float* __restrict__ U2,
    const float* __restrict__ bi2, const float* __restrict__ br2,
    const float* __restrict__ Wd, const float* __restrict__ bd,
    bf16* xhi, bf16* xlo, bf16* h1hi, bf16* h1lo, bf16* h2hi, bf16* h2lo,
    float* head, int* bars, float* out)
{
    extern __shared__ char smc[];
    u32 sb = (u32)__cvta_generic_to_shared(smc);
    bf16* wh = (bf16*)(smc + OFF_WH);
    bf16* wl = (bf16*)(smc + OFF_WL);
    float* scrA = (float*)(smc + OFF_SCRA);
    float* scrB = (float*)(smc + OFF_SCRB);

    const int tid = threadIdx.x, wid = tid >> 5;
    const int mt = wid & 7, nt = wid >> 3;
    const int cta = blockIdx.x;
    const bool isL1 = cta < 64;
    const int ug = cta & 63;
    const int inK = isL1 ? FF : UU;
    const int Ktot = inK + UU;
    const int inCh = inK / 32, nch = Ktot / 32;

    if (tid == 0) {
        asm volatile("st.global.relaxed.gpu.u32 [%0], %1;" :: "l"(bars + TT + 2), "r"(0) : "memory");
        #pragma unroll
        for (int m = 0; m < 3; m++)
            asm volatile("mbarrier.init.shared.b64 [%0], 1;" :: "r"(sb + OFF_CTRL + m * 8) : "memory");
    }
    if (tid < BB) {
        bf16* Hh = isL1 ? h1hi : h2hi;
        bf16* Hl = isL1 ? h1lo : h2lo;
        uint4 z4 = make_uint4(0, 0, 0, 0);
        for (int par = 0; par < 2; par++) {
            size_t o = (((size_t)par * 16 + (ug >> 2)) * BB + tid) * 32 + (ug & 3) * 8;
            *reinterpret_cast<uint4*>(Hh + o) = z4;
            *reinterpret_cast<uint4*>(Hl + o) = z4;
        }
    }
    // weights: cols 0..23 = gates (col = g*8+u), cols 24..31 zero
    {
        const float* WA = isL1 ? W1 : W2;
        const float* WB = isL1 ? U1 : U2;
        for (int idx = tid; idx < Ktot * 24; idx += NTHR) {
            int r = idx / 24, c = idx - r * 24;
            int gcol = (c >> 3) * UU + ug * 8 + (c & 7);
            float v = (r < inK) ? WA[(size_t)r * G3 + gcol] : WB[(size_t)(r - inK) * G3 + gcol];
            bf16 h = __float2bfloat16(v);
            wh[r * 32 + c] = h;
            wl[r * 32 + c] = __float2bfloat16(v - __bfloat162float(h));
        }
        for (int idx = tid; idx < Ktot * 8; idx += NTHR) {
            int r = idx / 8, c = 24 + (idx & 7);
            wh[r * 32 + c] = __float2bfloat16(0.f);
            wl[r * 32 + c] = __float2bfloat16(0.f);
        }
    }
    float bZ[8], bR[8], bHx[8], bHr[8], hold[8];
    {
        const float* bi = isL1 ? bi1 : bi2;
        const float* br = isL1 ? br1 : br2;
        #pragma unroll
        for (int u = 0; u < 8; u++) {
            int j = ug * 8 + u;
            bZ[u] = bi[j] + br[j];
            bR[u] = bi[UU + j] + br[UU + j];
            bHx[u] = bi[2 * UU + j];
            bHr[u] = br[2 * UU + j];
            hold[u] = 0.0f;
        }
    }
    __syncthreads();
    grid_barrier(bars, 0);

    u32 pc[3] = {0, 0, 0};   // per-buffer phase counters (persist across supersteps)

    #pragma unroll 1
    for (int t = 0; t <= TT; t++) {
        const bool act = isL1 ? (t < TT) : (t > 0);
        if (act) {
            const bf16 *SAh, *SAl, *SBh, *SBl;
            if (isL1) {
                SAh = xhi + (size_t)t * 4 * BB * 32;  SAl = xlo + (size_t)t * 4 * BB * 32;
                SBh = h1hi + (size_t)(t & 1) * 16 * BB * 32;
                SBl = h1lo + (size_t)(t & 1) * 16 * BB * 32;
            } else {
                SAh = h1hi + (size_t)(t & 1) * 16 * BB * 32;
                SAl = h1lo + (size_t)(t & 1) * 16 * BB * 32;
                SBh = h2hi + (size_t)((t + 1) & 1) * 16 * BB * 32;
                SBl = h2lo + (size_t)((t + 1) & 1) * 16 * BB * 32;
            }
            auto issue = [&](int i) {
                if (tid != 0) return;
                const bf16 *sh, *sl; int kb;
                if (i < inCh) { sh = SAh; sl = SAl; kb = i; }
                else          { sh = SBh; sl = SBl; kb = i - inCh; }
                int buf = i % 3;
                u32 mb = sb + OFF_CTRL + (u32)buf * 8;
                u32 dh = sb + OFF_ACT + (u32)buf * 16384u;
                asm volatile("mbarrier.arrive.expect_tx.shared.b64 _, [%0], %1;"
                             :: "r"(mb), "r"(16384u) : "memory");
                bulk_cp(dh,         sh + (size_t)kb * BB * 32, mb);
                bulk_cp(dh + 8192u, sl + (size_t)kb * BB * 32, mb);
            };

            FragC accA, accB;
            wmma::fill_fragment(accA, 0.0f);
            wmma::fill_fragment(accB, 0.0f);

            issue(0);
            issue(1);
            #pragma unroll 1
            for (int ch = 0; ch < nch; ch++) {
                int buf = ch % 3;
                mwait(sb + OFF_CTRL + (u32)buf * 8, pc[buf] & 1);
                pc[buf]++;
                __syncthreads();           // all consumed ch-1; safe to reissue its buffer
                if (ch + 2 < nch) issue(ch + 2);
                const bf16* Ah = (const bf16*)(smc + OFF_ACT + buf * 16384);
                const bf16* Al = Ah + 4096;
                FragC* acc = (ch < inCh) ? &accA : &accB;
                #pragma unroll
                for (int kt = 0; kt < 2; kt++) {
                    FragA fah, fal;
                    FragB fbh, fbl;
                    wmma::load_matrix_sync(fah, Ah + (mt * 16) * 32 + kt * 16, 32);
                    wmma::load_matrix_sync(fal, Al + (mt * 16) * 32 + kt * 16, 32);
                    int krow = ch * 32 + kt * 16;
                    wmma::load_matrix_sync(fbh, wh + krow * 32 + nt * 16, 32);
                    wmma::load_matrix_sync(fbl, wl + krow * 32 + nt * 16, 32);
                    wmma::mma_sync(*acc, fah, fbh, *acc);
                    wmma::mma_sync(*acc, fah, fbl, *acc);
                    wmma::mma_sync(*acc, fal, fbh, *acc);
                }
            }
            __syncthreads();   // act buffers dead; scratch overlay safe

            wmma::store_matrix_sync(scrA + (mt * 16) * 36 + nt * 16, accA, 36, wmma::mem_row_major);
            wmma::store_matrix_sync(scrB + (mt * 16) * 36 + nt * 16, accB, 36, wmma::mem_row_major);
            __syncthreads();

            if (tid < BB) {
                bf16 nh[8], nl[8];
                const float* ra = scrA + tid * 36;
                const float* rb = scrB + tid * 36;
                #pragma unroll
                for (int u = 0; u < 8; u++) {
                    float zv = sigm(ra[u] + rb[u] + bZ[u]);
                    float rv = sigm(ra[8 + u] + rb[8 + u] + bR[u]);
                    float cand = fmaxf(ra[16 + u] + bHx[u] + rv * (rb[16 + u] + bHr[u]), 0.0f);
                    float hn = zv * hold[u] + (1.0f - zv) * cand;
                    hold[u] = hn;
                    nh[u] = __float2bfloat16(hn);
                    nl[u] = __float2bfloat16(hn - __bfloat162float(nh[u]));
                }
                int wpar = isL1 ? ((t + 1) & 1) : (t & 1);
                size_t o = (((size_t)wpar * 16 + (ug >> 2)) * BB + tid) * 32 + (ug & 3) * 8;
                bf16* Dh = (isL1 ? h1hi : h2hi) + o;
                bf16* Dl = (isL1 ? h1lo : h2lo) + o;
                *reinterpret_cast<uint4*>(Dh) = *reinterpret_cast<uint4*>(nh);
                *reinterpret_cast<uint4*>(Dl) = *reinterpret_cast<uint4*>(nl);
            }
            __syncthreads();   // scratch reads done before next superstep reuses buffers
        }
        grid_barrier(bars, 1 + t);
    }

    // head: L2 CTAs hold h2(final) in regs -> partials -> CTA0 reduces
    if (!isL1 && tid < BB) {
        float acc = 0.0f;
        #pragma unroll
        for (int u = 0; u < 8; u++)
            acc += hold[u] * __ldg(&Wd[ug * 8 + u]);
        head[ug * BB + tid] = acc;
    }
    grid_barrier(bars, TT + 2);
    if (cta == 0 && tid < BB) {
        float acc = bd[0];
        #pragma unroll 8
        for (int c = 0; c < 64; c++)
            acc += head[c * BB + tid];
        out[tid] = acc;
    }
    __syncthreads();
    if (tid == 0) {
        #pragma unroll
        for (int m = 0; m < 3; m++)
            asm volatile("mbarrier.inval.shared.b64 [%0];" :: "r"(sb + OFF_CTRL + m * 8) : "memory");
    }
}

// x (B,T,F) fp32 -> (t, chunk, b, 32) bf16 hi/lo
__global__ void prep_x(const float* __restrict__ x, bf16* __restrict__ xh, bf16* __restrict__ xl)
{
    const int t = blockIdx.x, bq = blockIdx.y;
    for (int idx = threadIdx.x; idx < 32 * FF; idx += 128) {
        int b = bq * 32 + (idx >> 7), f = idx & 127;
        float v = x[((size_t)b * TT + t) * FF + f];
        bf16 h = __float2bfloat16(v);
        size_t o = (((size_t)t * 4 + (f >> 5)) * BB + b) * 32 + (f & 31);
        xh[o] = h;
        xl[o] = __float2bfloat16(v - __bfloat162float(h));
    }
}

extern "C" void kernel_launch(void* const* d_in, const int* in_sizes, int n_in,
                              void* d_out, int out_size)
{
    const float* x   = (const float*)d_in[0];
    const float* W1  = (const float*)d_in[1];
    const float* U1  = (const float*)d_in[2];
    const float* bi1 = (const float*)d_in[3];
    const float* br1 = (const float*)d_in[4];
    const float* W2  = (const float*)d_in[5];
    const float* U2  = (const float*)d_in[6];
    const float* bi2 = (const float*)d_in[7];
    const float* br2 = (const float*)d_in[8];
    const float* Wd  = (const float*)d_in[9];
    const float* bd  = (const float*)d_in[10];
    float* out = (float*)d_out;

    bf16 *xh, *xl, *h1h, *h1l, *h2h, *h2l; float* hd; int* bars;
    cudaGetSymbolAddress((void**)&xh, g_xhi);
    cudaGetSymbolAddress((void**)&xl, g_xlo);
    cudaGetSymbolAddress((void**)&h1h, g_h1hi);
    cudaGetSymbolAddress((void**)&h1l, g_h1lo);
    cudaGetSymbolAddress((void**)&h2h, g_h2hi);
    cudaGetSymbolAddress((void**)&h2l, g_h2lo);
    cudaGetSymbolAddress((void**)&hd, g_head);
    cudaGetSymbolAddress((void**)&bars, g_bar);

    cudaFuncSetAttribute(gru_wmma, cudaFuncAttributeMaxDynamicSharedMemorySize, SMEM_BYTES);

    prep_x<<<dim3(TT, 4), 128>>>(x, xh, xl);
    gru_wmma<<<NCTA, NTHR, SMEM_BYTES>>>(W1, U1, bi1, br1, W2, U2, bi2, br2, Wd, bd,
                                         xh, xl, h1h, h1l, h2h, h2l, hd, bars, out);
}

// round 17
// speedup vs baseline: 1.1987x; 1.1987x over previous
#include <cuda_runtime.h>
#include <cuda_bf16.h>
#include <mma.h>
#include <cstdint>

using namespace nvcuda;
typedef unsigned int u32;
typedef __nv_bfloat16 bf16;

#define BB 128
#define TT 512
#define FF 128
#define UU 512
#define G3 1536
#define NCTA 128
#define NTHR 544          // 16 consumer warps + 1 producer warp
#define NBUF 6

// SMEM byte offsets
#define OFF_WH    0            // weights hi (<=64KB)
#define OFF_WL    65536        // weights lo
#define OFF_ACT   131072       // 6 buffers x 16384 (hi 8KB + lo 8KB)
#define OFF_FULL  229376       // 6 full mbarriers
#define OFF_EMPTY 229424       // 6 empty mbarriers
#define OFF_SCRA  OFF_ACT      // scratch overlays act bufs post-loop (guarded by sync)
#define OFF_SCRB  (OFF_ACT + 18432)
#define SMEM_BYTES 229472

__device__ __align__(128) bf16 g_xhi[(size_t)TT * 4 * BB * 32];   // (t, chunk, b, 32)
__device__ __align__(128) bf16 g_xlo[(size_t)TT * 4 * BB * 32];
__device__ __align__(128) bf16 g_h1hi[2 * 16 * BB * 32];          // (par, chunk, b, 32)
__device__ __align__(128) bf16 g_h1lo[2 * 16 * BB * 32];
__device__ __align__(128) bf16 g_h2hi[2 * 16 * BB * 32];
__device__ __align__(128) bf16 g_h2lo[2 * 16 * BB * 32];
__device__ __align__(128) float g_head[64 * BB];
__device__ __align__(128) int  g_bar[TT + 4];

__device__ __forceinline__ float sigm(float v) { return 1.0f / (1.0f + __expf(-v)); }
__device__ __forceinline__ void bulk_cp(u32 dst, const void* src, u32 mbar) {
    asm volatile("cp.async.bulk.shared::cta.global.mbarrier::complete_tx::bytes [%0], [%1], %2, [%3];"
                 :: "r"(dst), "l"(src), "r"(8192u), "r"(mbar) : "memory");
}
__device__ __forceinline__ void mwait(u32 mb, u32 par) {
    u32 done = 0;
    do {
        asm volatile("{\n\t.reg .pred p;\n\t"
                     "mbarrier.try_wait.parity.acquire.cta.shared::cta.b64 p, [%1], %2, 0x989680;\n\t"
                     "selp.b32 %0,1,0,p;\n\t}" : "=r"(done) : "r"(mb), "r"(par) : "memory");
    } while (!done);
}
__device__ __forceinline__ void grid_barrier(int* bars, int s) {
    __syncthreads();
    if (threadIdx.x == 0) {
        asm volatile("red.release.gpu.global.add.u32 [%0], 1;" :: "l"(bars + s) : "memory");
        int v;
        do { asm volatile("ld.acquire.gpu.global.u32 %0, [%1];" : "=r"(v) : "l"(bars + s) : "memory"); }
        while (v < NCTA);
        if (s >= 1)
            asm volatile("st.global.relaxed.gpu.u32 [%0], %1;" :: "l"(bars + s - 1), "r"(0) : "memory");
    }
    __syncthreads();
}

typedef wmma::fragment<wmma::matrix_a, 16, 16, 16, bf16, wmma::row_major> FragA;
typedef wmma::fragment<wmma::matrix_b, 16, 16, 16, bf16, wmma::row_major> FragB;
typedef wmma::fragment<wmma::accumulator, 16, 16, 16, float> FragC;

__global__ void __launch_bounds__(NTHR, 1) gru_wmma(
    const float* __restrict__ W1, const float* __restrict__ U1,
    const float* __restrict__ bi1, const float* __restrict__ br1,
    const float* __restrict__ W2, const float* __restrict__ U2,
    const float* __restrict__ bi2, const float* __restrict__ br2,
    const float* __restrict__ Wd, const float* __restrict__ bd,
    bf16* xhi, bf16* xlo, bf16* h1hi, bf16* h1lo, bf16* h2hi, bf16* h2lo,
    float* head, int* bars, float* out)
{
    extern __shared__ char smc[];
    u32 sb = (u32)__cvta_generic_to_shared(smc);
    bf16* wh = (bf16*)(smc + OFF_WH);
    bf16* wl = (bf16*)(smc + OFF_WL);
    float* scrA = (float*)(smc + OFF_SCRA);
    float* scrB = (float*)(smc + OFF_SCRB);

    const int tid = threadIdx.x, wid = tid >> 5, lane = tid & 31;
    const bool prod = (wid == 16);
    const int mt = wid & 7, nt = (wid >> 3) & 1;
    const int cta = blockIdx.x;
    const bool isL1 = cta < 64;
    const int ug = cta & 63;
    const int inK = isL1 ? FF : UU;
    const int Ktot = inK + UU;
    const int inCh = inK / 32, nch = Ktot / 32;

    if (tid == 0) {
        asm volatile("st.global.relaxed.gpu.u32 [%0], %1;" :: "l"(bars + TT + 2), "r"(0) : "memory");
        #pragma unroll
        for (int m = 0; m < NBUF; m++) {
            asm volatile("mbarrier.init.shared.b64 [%0], 1;"  :: "r"(sb + OFF_FULL  + m * 8) : "memory");
            asm volatile("mbarrier.init.shared.b64 [%0], 16;" :: "r"(sb + OFF_EMPTY + m * 8) : "memory");
        }
    }
    if (tid < BB) {
        bf16* Hh = isL1 ? h1hi : h2hi;
        bf16* Hl = isL1 ? h1lo : h2lo;
        uint4 z4 = make_uint4(0, 0, 0, 0);
        for (int par = 0; par < 2; par++) {
            size_t o = (((size_t)par * 16 + (ug >> 2)) * BB + tid) * 32 + (ug & 3) * 8;
            *reinterpret_cast<uint4*>(Hh + o) = z4;
            *reinterpret_cast<uint4*>(Hl + o) = z4;
        }
    }
    // weights: cols 0..23 = gates (col = g*8+u), cols 24..31 zero
    {
        const float* WA = isL1 ? W1 : W2;
        const float* WB = isL1 ? U1 : U2;
        for (int idx = tid; idx < Ktot * 24; idx += NTHR) {
            int r = idx / 24, c = idx - r * 24;
            int gcol = (c >> 3) * UU + ug * 8 + (c & 7);
            float v = (r < inK) ? WA[(size_t)r * G3 + gcol] : WB[(size_t)(r - inK) * G3 + gcol];
            bf16 h = __float2bfloat16(v);
            wh[r * 32 + c] = h;
            wl[r * 32 + c] = __float2bfloat16(v - __bfloat162float(h));
        }
        for (int idx = tid; idx < Ktot * 8; idx += NTHR) {
            int r = idx / 8, c = 24 + (idx & 7);
            wh[r * 32 + c] = __float2bfloat16(0.f);
            wl[r * 32 + c] = __float2bfloat16(0.f);
        }
    }
    float bZ[8], bR[8], bHx[8], bHr[8], hold[8];
    {
        const float* bi = isL1 ? bi1 : bi2;
        const float* br = isL1 ? br1 : br2;
        #pragma unroll
        for (int u = 0; u < 8; u++) {
            int j = ug * 8 + u;
            bZ[u] = bi[j] + br[j];
            bR[u] = bi[UU + j] + br[UU + j];
            bHx[u] = bi[2 * UU + j];
            bHr[u] = br[2 * UU + j];
            hold[u] = 0.0f;
        }
    }
    __syncthreads();
    grid_barrier(bars, 0);

    u32 ci0 = 0;   // global chunk cursor base (uniform across threads)

    #pragma unroll 1
    for (int t = 0; t <= TT; t++) {
        const bool act = isL1 ? (t < TT) : (t > 0);
        if (act) {
            const bf16 *SAh, *SAl, *SBh, *SBl;
            if (isL1) {
                SAh = xhi + (size_t)t * 4 * BB * 32;  SAl = xlo + (size_t)t * 4 * BB * 32;
                SBh = h1hi + (size_t)(t & 1) * 16 * BB * 32;
                SBl = h1lo + (size_t)(t & 1) * 16 * BB * 32;
            } else {
                SAh = h1hi + (size_t)(t & 1) * 16 * BB * 32;
                SAl = h1lo + (size_t)(t & 1) * 16 * BB * 32;
                SBh = h2hi + (size_t)((t + 1) & 1) * 16 * BB * 32;
                SBl = h2lo + (size_t)((t + 1) & 1) * 16 * BB * 32;
            }

            FragC accA, accB;
            if (prod) {
                // producer warp: issue all chunks, gated by empty barriers
                #pragma unroll 1
                for (int ch = 0; ch < nch; ch++) {
                    u32 ci = ci0 + ch, buf = ci % NBUF;
                    u32 eph = ((ci / NBUF) & 1u) ^ 1u;   // producer phase starts at 1
                    mwait(sb + OFF_EMPTY + buf * 8, eph);
                    if (lane == 0) {
                        const bf16 *sh, *sl; int kb;
                        if (ch < inCh) { sh = SAh; sl = SAl; kb = ch; }
                        else           { sh = SBh; sl = SBl; kb = ch - inCh; }
                        u32 mb = sb + OFF_FULL + buf * 8;
                        u32 dh = sb + OFF_ACT + buf * 16384u;
                        asm volatile("mbarrier.arrive.expect_tx.shared.b64 _, [%0], %1;"
                                     :: "r"(mb), "r"(16384u) : "memory");
                        bulk_cp(dh,         sh + (size_t)kb * BB * 32, mb);
                        bulk_cp(dh + 8192u, sl + (size_t)kb * BB * 32, mb);
                    }
                }
            } else {
                // consumer warps: free-run through chunks
                wmma::fill_fragment(accA, 0.0f);
                wmma::fill_fragment(accB, 0.0f);
                #pragma unroll 1
                for (int ch = 0; ch < nch; ch++) {
                    u32 ci = ci0 + ch, buf = ci % NBUF;
                    u32 fph = (ci / NBUF) & 1u;
                    mwait(sb + OFF_FULL + buf * 8, fph);
                    const bf16* Ah = (const bf16*)(smc + OFF_ACT + buf * 16384);
                    const bf16* Al = Ah + 4096;
                    FragC* acc = (ch < inCh) ? &accA : &accB;
                    #pragma unroll
                    for (int kt = 0; kt < 2; kt++) {
                        FragA fah, fal;
                        FragB fbh, fbl;
                        wmma::load_matrix_sync(fah, Ah + (mt * 16) * 32 + kt * 16, 32);
                        wmma::load_matrix_sync(fal, Al + (mt * 16) * 32 + kt * 16, 32);
                        int krow = ch * 32 + kt * 16;
                        wmma::load_matrix_sync(fbh, wh + krow * 32 + nt * 16, 32);
                        wmma::load_matrix_sync(fbl, wl + krow * 32 + nt * 16, 32);
                        wmma::mma_sync(*acc, fah, fbh, *acc);
                        wmma::mma_sync(*acc, fah, fbl, *acc);
                        wmma::mma_sync(*acc, fal, fbh, *acc);
                    }
                    if (lane == 0)
                        asm volatile("mbarrier.arrive.shared.b64 _, [%0];"
                                     :: "r"(sb + OFF_EMPTY + buf * 8) : "memory");
                }
            }
            ci0 += nch;

            // ALL warps (incl. producer) rendezvous: every consumer has finished
            // reading every act buffer -> overlaying scratch on them is now safe.
            __syncthreads();
            if (!prod) {
                wmma::store_matrix_sync(scrA + (mt * 16) * 36 + nt * 16, accA, 36, wmma::mem_row_major);
                wmma::store_matrix_sync(scrB + (mt * 16) * 36 + nt * 16, accB, 36, wmma::mem_row_major);
            }
            __syncthreads();

            if (tid < BB) {
                bf16 nh[8], nl[8];
                const float* ra = scrA + tid * 36;
                const float* rb = scrB + tid * 36;
                #pragma unroll
                for (int u = 0; u < 8; u++) {
                    float zv = sigm(ra[u] + rb[u] + bZ[u]);
                    float rv = sigm(ra[8 + u] + rb[8 + u] + bR[u]);
                    float cand = fmaxf(ra[16 + u] + bHx[u] + rv * (rb[16 + u] + bHr[u]), 0.0f);
                    float hn = zv * hold[u] + (1.0f - zv) * cand;
                    hold[u] = hn;
                    nh[u] = __float2bfloat16(hn);
                    nl[u] = __float2bfloat16(hn - __bfloat162float(nh[u]));
                }
                int wpar = isL1 ? ((t + 1) & 1) : (t & 1);
                size_t o = (((size_t)wpar * 16 + (ug >> 2)) * BB + tid) * 32 + (ug & 3) * 8;
                bf16* Dh = (isL1 ? h1hi : h2hi) + o;
                bf16* Dl = (isL1 ? h1lo : h2lo) + o;
                *reinterpret_cast<uint4*>(Dh) = *reinterpret_cast<uint4*>(nh);
                *reinterpret_cast<uint4*>(Dl) = *reinterpret_cast<uint4*>(nl);
            }
            __syncthreads();   // scratch reads done before buffers refill next superstep
        }
        grid_barrier(bars, 1 + t);
    }

    // head: L2 CTAs hold h2(final) in regs -> partials -> CTA0 reduces
    if (!isL1 && tid < BB) {
        float acc = 0.0f;
        #pragma unroll
        for (int u = 0; u < 8; u++)
            acc += hold[u] * __ldg(&Wd[ug * 8 + u]);
        head[ug * BB + tid] = acc;
    }
    grid_barrier(bars, TT + 2);
    if (cta == 0 && tid < BB) {
        float acc = bd[0];
        #pragma unroll 8
        for (int c = 0; c < 64; c++)
            acc += head[c * BB + tid];
        out[tid] = acc;
    }
    __syncthreads();
    if (tid == 0) {
        #pragma unroll
        for (int m = 0; m < NBUF; m++) {
            asm volatile("mbarrier.inval.shared.b64 [%0];" :: "r"(sb + OFF_FULL  + m * 8) : "memory");
            asm volatile("mbarrier.inval.shared.b64 [%0];" :: "r"(sb + OFF_EMPTY + m * 8) : "memory");
        }
    }
}

// x (B,T,F) fp32 -> (t, chunk, b, 32) bf16 hi/lo
__global__ void prep_x(const float* __restrict__ x, bf16* __restrict__ xh, bf16* __restrict__ xl)
{
    const int t = blockIdx.x, bq = blockIdx.y;
    for (int idx = threadIdx.x; idx < 32 * FF; idx += 128) {
        int b = bq * 32 + (idx >> 7), f = idx & 127;
        float v = x[((size_t)b * TT + t) * FF + f];
        bf16 h = __float2bfloat16(v);
        size_t o = (((size_t)t * 4 + (f >> 5)) * BB + b) * 32 + (f & 31);
        xh[o] = h;
        xl[o] = __float2bfloat16(v - __bfloat162float(h));
    }
}

extern "C" void kernel_launch(void* const* d_in, const int* in_sizes, int n_in,
                              void* d_out, int out_size)
{
    const float* x   = (const float*)d_in[0];
    const float* W1  = (const float*)d_in[1];
    const float* U1  = (const float*)d_in[2];
    const float* bi1 = (const float*)d_in[3];
    const float* br1 = (const float*)d_in[4];
    const float* W2  = (const float*)d_in[5];
    const float* U2  = (const float*)d_in[6];
    const float* bi2 = (const float*)d_in[7];
    const float* br2 = (const float*)d_in[8];
    const float* Wd  = (const float*)d_in[9];
    const float* bd  = (const float*)d_in[10];
    float* out = (float*)d_out;

    bf16 *xh, *xl, *h1h, *h1l, *h2h, *h2l; float* hd; int* bars;
    cudaGetSymbolAddress((void**)&xh, g_xhi);
    cudaGetSymbolAddress((void**)&xl, g_xlo);
    cudaGetSymbolAddress((void**)&h1h, g_h1hi);
    cudaGetSymbolAddress((void**)&h1l, g_h1lo);
    cudaGetSymbolAddress((void**)&h2h, g_h2hi);
    cudaGetSymbolAddress((void**)&h2l, g_h2lo);
    cudaGetSymbolAddress((void**)&hd, g_head);
    cudaGetSymbolAddress((void**)&bars, g_bar);

    cudaFuncSetAttribute(gru_wmma, cudaFuncAttributeMaxDynamicSharedMemorySize, SMEM_BYTES);

    prep_x<<<dim3(TT, 4), 128>>>(x, xh, xl);
    gru_wmma<<<NCTA, NTHR, SMEM_BYTES>>>(W1, U1, bi1, br1, W2, U2, bi2, br2, Wd, bd,
                                         xh, xl, h1h, h1l, h2h, h2l, hd, bars, out);
}